// round 3
// baseline (speedup 1.0000x reference)
#include <cuda_runtime.h>

// ElementwiseTensorProd_o0: per token t (262144 tokens), rank R=128:
//   out[t, 0:128]   = z0l[t, :] * z0r[t, :]
//   out[t, 128:256] = sum_{m=0..2} z1l[t, m, :] * z1r[t, m, :]
//
// Pure streaming, HBM-bound. float4 vectorization, 1 thread = 4 channels of
// one token; 32 consecutive lanes cover one token's full rank -> all global
// accesses are coalesced 128B lines.

#define TOKENS 262144
#define RANK 128
#define V4_PER_ROW (RANK / 4)            // 32 float4 per 128-float row
#define THREADS_PER_BLOCK 256

__global__ void __launch_bounds__(THREADS_PER_BLOCK)
etp_o0_kernel(const float4* __restrict__ z0l,
              const float4* __restrict__ z1l,
              const float4* __restrict__ z0r,
              const float4* __restrict__ z1r,
              float4* __restrict__ out)
{
    // Global thread id over TOKENS * 32 float4-slots.
    unsigned int i = blockIdx.x * THREADS_PER_BLOCK + threadIdx.x;
    // i < TOKENS*32 guaranteed by exact grid sizing (TOKENS*32 % 256 == 0).

    unsigned int c4 = i & (V4_PER_ROW - 1);   // 0..31 within rank
    unsigned int t  = i >> 5;                 // token id

    // ---- path (0,0,0): scalar * scalar ----
    const unsigned int i0 = t * V4_PER_ROW + c4;
    float4 a0 = z0l[i0];
    float4 b0 = z0r[i0];

    // ---- path (1,1,0): contract irrep dim m=0..2 ----
    // z1 layout: (TOKENS, 3, RANK) -> index t*96 + m*32 + c4 (in float4 units)
    const unsigned int i1 = t * (3 * V4_PER_ROW) + c4;
    float4 a1 = z1l[i1];
    float4 b1 = z1r[i1];
    float4 a2 = z1l[i1 + V4_PER_ROW];
    float4 b2 = z1r[i1 + V4_PER_ROW];
    float4 a3 = z1l[i1 + 2 * V4_PER_ROW];
    float4 b3 = z1r[i1 + 2 * V4_PER_ROW];

    float4 o00;
    o00.x = a0.x * b0.x;
    o00.y = a0.y * b0.y;
    o00.z = a0.z * b0.z;
    o00.w = a0.w * b0.w;

    float4 o11;
    o11.x = fmaf(a1.x, b1.x, fmaf(a2.x, b2.x, a3.x * b3.x));
    o11.y = fmaf(a1.y, b1.y, fmaf(a2.y, b2.y, a3.y * b3.y));
    o11.z = fmaf(a1.z, b1.z, fmaf(a2.z, b2.z, a3.z * b3.z));
    o11.w = fmaf(a1.w, b1.w, fmaf(a2.w, b2.w, a3.w * b3.w));

    // Output layout: (TOKENS, 2*RANK) -> 64 float4 per token.
    const unsigned int o = t * (2 * V4_PER_ROW) + c4;
    out[o] = o00;
    out[o + V4_PER_ROW] = o11;
}

extern "C" void kernel_launch(void* const* d_in, const int* in_sizes, int n_in,
                              void* d_out, int out_size)
{
    (void)in_sizes; (void)n_in; (void)out_size;
    const float4* z0l = (const float4*)d_in[0];
    const float4* z1l = (const float4*)d_in[1];
    const float4* z0r = (const float4*)d_in[2];
    const float4* z1r = (const float4*)d_in[3];
    float4* out = (float4*)d_out;

    const unsigned int total_threads = TOKENS * V4_PER_ROW;      // 8,388,608
    const unsigned int blocks = total_threads / THREADS_PER_BLOCK; // 32768

    etp_o0_kernel<<<blocks, THREADS_PER_BLOCK>>>(z0l, z1l, z0r, z1r, out);
}

// round 4
// speedup vs baseline: 1.0051x; 1.0051x over previous
#include <cuda_runtime.h>

// ElementwiseTensorProd_o0: per token t (262144 tokens), rank R=128:
//   out[t, 0:128]   = z0l[t, :] * z0r[t, :]
//   out[t, 128:256] = sum_{m=0..2} z1l[t, m, :] * z1r[t, m, :]
//
// Zero-reuse HBM stream at the traffic minimum (1.342 GB). This round:
//  - 2 token-slots per thread, all 16 LDG.128s front-batched (deeper MLP,
//    half the waves).
//  - __ldcs / __stcs evict-first policy: no reuse, keep L2 clean so dirty
//    writebacks don't fight inflight reads.

#define TOKENS 262144
#define RANK 128
#define V4_PER_ROW (RANK / 4)            // 32 float4 per 128-float row
#define THREADS_PER_BLOCK 256

#define TOTAL_SLOTS (TOKENS * V4_PER_ROW)       // 8,388,608 float4-slots
#define HALF_SLOTS  (TOTAL_SLOTS / 2)           // 4,194,304

__device__ __forceinline__ float4 ldcs4(const float4* p) { return __ldcs(p); }

__global__ void __launch_bounds__(THREADS_PER_BLOCK)
etp_o0_kernel(const float4* __restrict__ z0l,
              const float4* __restrict__ z1l,
              const float4* __restrict__ z0r,
              const float4* __restrict__ z1r,
              float4* __restrict__ out)
{
    // Two slots per thread: slot i (first half of tokens) and i + HALF_SLOTS
    // (second half). Both streams stay perfectly coalesced per warp.
    const unsigned int i  = blockIdx.x * THREADS_PER_BLOCK + threadIdx.x;
    const unsigned int iB = i + HALF_SLOTS;

    const unsigned int c4A = i  & (V4_PER_ROW - 1);
    const unsigned int tA  = i  >> 5;
    const unsigned int c4B = iB & (V4_PER_ROW - 1);
    const unsigned int tB  = iB >> 5;

    const unsigned int i0A = tA * V4_PER_ROW + c4A;
    const unsigned int i0B = tB * V4_PER_ROW + c4B;
    const unsigned int i1A = tA * (3 * V4_PER_ROW) + c4A;
    const unsigned int i1B = tB * (3 * V4_PER_ROW) + c4B;

    // ---- front-batch all 16 loads (evict-first) ----
    float4 a0A = ldcs4(z0l + i0A);
    float4 b0A = ldcs4(z0r + i0A);
    float4 a1A = ldcs4(z1l + i1A);
    float4 b1A = ldcs4(z1r + i1A);
    float4 a2A = ldcs4(z1l + i1A + V4_PER_ROW);
    float4 b2A = ldcs4(z1r + i1A + V4_PER_ROW);
    float4 a3A = ldcs4(z1l + i1A + 2 * V4_PER_ROW);
    float4 b3A = ldcs4(z1r + i1A + 2 * V4_PER_ROW);

    float4 a0B = ldcs4(z0l + i0B);
    float4 b0B = ldcs4(z0r + i0B);
    float4 a1B = ldcs4(z1l + i1B);
    float4 b1B = ldcs4(z1r + i1B);
    float4 a2B = ldcs4(z1l + i1B + V4_PER_ROW);
    float4 b2B = ldcs4(z1r + i1B + V4_PER_ROW);
    float4 a3B = ldcs4(z1l + i1B + 2 * V4_PER_ROW);
    float4 b3B = ldcs4(z1r + i1B + 2 * V4_PER_ROW);

    // ---- compute slot A ----
    float4 o00A, o11A;
    o00A.x = a0A.x * b0A.x;  o00A.y = a0A.y * b0A.y;
    o00A.z = a0A.z * b0A.z;  o00A.w = a0A.w * b0A.w;
    o11A.x = fmaf(a1A.x, b1A.x, fmaf(a2A.x, b2A.x, a3A.x * b3A.x));
    o11A.y = fmaf(a1A.y, b1A.y, fmaf(a2A.y, b2A.y, a3A.y * b3A.y));
    o11A.z = fmaf(a1A.z, b1A.z, fmaf(a2A.z, b2A.z, a3A.z * b3A.z));
    o11A.w = fmaf(a1A.w, b1A.w, fmaf(a2A.w, b2A.w, a3A.w * b3A.w));

    const unsigned int oA = tA * (2 * V4_PER_ROW) + c4A;
    __stcs(out + oA, o00A);
    __stcs(out + oA + V4_PER_ROW, o11A);

    // ---- compute slot B ----
    float4 o00B, o11B;
    o00B.x = a0B.x * b0B.x;  o00B.y = a0B.y * b0B.y;
    o00B.z = a0B.z * b0B.z;  o00B.w = a0B.w * b0B.w;
    o11B.x = fmaf(a1B.x, b1B.x, fmaf(a2B.x, b2B.x, a3B.x * b3B.x));
    o11B.y = fmaf(a1B.y, b1B.y, fmaf(a2B.y, b2B.y, a3B.y * b3B.y));
    o11B.z = fmaf(a1B.z, b1B.z, fmaf(a2B.z, b2B.z, a3B.z * b3B.z));
    o11B.w = fmaf(a1B.w, b1B.w, fmaf(a2B.w, b2B.w, a3B.w * b3B.w));

    const unsigned int oB = tB * (2 * V4_PER_ROW) + c4B;
    __stcs(out + oB, o00B);
    __stcs(out + oB + V4_PER_ROW, o11B);
}

extern "C" void kernel_launch(void* const* d_in, const int* in_sizes, int n_in,
                              void* d_out, int out_size)
{
    (void)in_sizes; (void)n_in; (void)out_size;
    const float4* z0l = (const float4*)d_in[0];
    const float4* z1l = (const float4*)d_in[1];
    const float4* z0r = (const float4*)d_in[2];
    const float4* z1r = (const float4*)d_in[3];
    float4* out = (float4*)d_out;

    const unsigned int threads_needed = HALF_SLOTS;                 // 4,194,304
    const unsigned int blocks = threads_needed / THREADS_PER_BLOCK; // 16384

    etp_o0_kernel<<<blocks, THREADS_PER_BLOCK>>>(z0l, z1l, z0r, z1r, out);
}